// round 10
// baseline (speedup 1.0000x reference)
#include <cuda_runtime.h>

// LSTM B=1024 T=512 F=40 H=50 + MLP head. Round 9 (= R8 resubmit, hardened).
//
// Kernel 1 (xg_kernel): xg[b*T+t][j] = bias_j + W_ih[j] . x[b][t]  (fp32,
//   f32x2, 2 gates/thread, W rows in registers, x tile staged in SMEM,
//   2-way token unroll to fill FMA dual-issue). Output in __device__ g_xg.
// Kernel 2 (lstm_kernel): recurrence with K=50 only (h . W_hh):
//   256 CTAs x 224 threads, RR=4 rows/CTA, 2 CTAs/SM. Thread j<200 holds
//   W_hh row (padded 56 -> 28 packed f32x2 regs), computes gate j for 4 rows
//   against broadcast ld.shared.v2.u64 of h; accumulator initialized from
//   prefetched xg (1 step lookahead, coalesced LDG). Two barriers/step,
//   gates exchanged through sG, c-state register-resident.

#define BB   1024
#define TT   512
#define FF   40
#define HH   50
#define GG   200
#define RR   4
#define KH   56           // padded h-K (50 + 6 pad) = 14 ull2
#define NTH  224
#define NGRID 256         // 1024 / RR

#define NT1  128
#define TPC  128          // tokens per CTA in kernel 1
#define NGRID1 ((BB * TT) / TPC)   // 4096

__device__ float g_xg[(size_t)BB * TT * GG];   // 420 MB scratch (.bss)

__device__ __forceinline__ unsigned long long pk2(float lo, float hi) {
    unsigned long long r;
    asm("mov.b64 %0, {%1, %2};" : "=l"(r) : "f"(lo), "f"(hi));
    return r;
}
__device__ __forceinline__ void upk2(unsigned long long v, float& lo, float& hi) {
    asm("mov.b64 {%0, %1}, %2;" : "=f"(lo), "=f"(hi) : "l"(v));
}
__device__ __forceinline__ unsigned long long f2fma(unsigned long long a,
                                                   unsigned long long b,
                                                   unsigned long long c) {
    unsigned long long d;
    asm("fma.rn.f32x2 %0, %1, %2, %3;" : "=l"(d) : "l"(a), "l"(b), "l"(c));
    return d;
}
__device__ __forceinline__ float tanh_f(float x) {
    float y;
    asm("tanh.approx.f32 %0, %1;" : "=f"(y) : "f"(x));
    return y;
}
__device__ __forceinline__ float sig_f(float x) {
    return fmaf(0.5f, tanh_f(0.5f * x), 0.5f);
}

// ================= kernel 1: xg precompute =================
__global__ __launch_bounds__(NT1, 4)
void xg_kernel(const float* __restrict__ x,   const float* __restrict__ Wih,
               const float* __restrict__ bih, const float* __restrict__ bhh)
{
    __shared__ __align__(16) float sX[TPC * FF];   // 20 KB token tile

    const int tid = threadIdx.x;
    const long tok0 = (long)blockIdx.x * TPC;      // token = b*T + t

    // stage x tile (contiguous TPC*40 floats)
    const float4* __restrict__ src = (const float4*)(x + tok0 * FF);
    #pragma unroll
    for (int i = tid; i < TPC * FF / 4; i += NT1)
        ((float4*)sX)[i] = src[i];

    // this thread's two gate rows j0, j0+1 in registers
    const int j0 = 2 * tid;
    unsigned long long w[40];
    float bsA = 0.f, bsB = 0.f;
    if (tid < 100) {
        #pragma unroll
        for (int k = 0; k < 20; ++k)
            w[k]      = pk2(Wih[j0 * FF + 2 * k],       Wih[j0 * FF + 2 * k + 1]);
        #pragma unroll
        for (int k = 0; k < 20; ++k)
            w[20 + k] = pk2(Wih[(j0 + 1) * FF + 2 * k], Wih[(j0 + 1) * FF + 2 * k + 1]);
        bsA = bih[j0]     + bhh[j0];
        bsB = bih[j0 + 1] + bhh[j0 + 1];
    }
    __syncthreads();

    if (tid < 100) {
        #pragma unroll 1
        for (int tt = 0; tt < TPC; tt += 2) {      // 2 tokens per iter
            const ulonglong2* __restrict__ xz0 =
                (const ulonglong2*)(sX + tt * FF);
            const ulonglong2* __restrict__ xz1 =
                (const ulonglong2*)(sX + (tt + 1) * FF);
            unsigned long long aA0 = pk2(bsA, 0.f), aB0 = pk2(bsB, 0.f);
            unsigned long long aA1 = pk2(bsA, 0.f), aB1 = pk2(bsB, 0.f);
            #pragma unroll
            for (int i = 0; i < 10; ++i) {
                ulonglong2 z0 = xz0[i];
                ulonglong2 z1 = xz1[i];
                unsigned long long wA0 = w[2 * i],      wA1 = w[2 * i + 1];
                unsigned long long wB0 = w[20 + 2 * i], wB1 = w[20 + 2 * i + 1];
                aA0 = f2fma(wA0, z0.x, aA0); aA0 = f2fma(wA1, z0.y, aA0);
                aB0 = f2fma(wB0, z0.x, aB0); aB0 = f2fma(wB1, z0.y, aB0);
                aA1 = f2fma(wA0, z1.x, aA1); aA1 = f2fma(wA1, z1.y, aA1);
                aB1 = f2fma(wB0, z1.x, aB1); aB1 = f2fma(wB1, z1.y, aB1);
            }
            float lo, hi, vA, vB;
            upk2(aA0, lo, hi); vA = lo + hi;
            upk2(aB0, lo, hi); vB = lo + hi;
            *(float2*)(g_xg + (tok0 + tt) * GG + j0)     = make_float2(vA, vB);
            upk2(aA1, lo, hi); vA = lo + hi;
            upk2(aB1, lo, hi); vB = lo + hi;
            *(float2*)(g_xg + (tok0 + tt + 1) * GG + j0) = make_float2(vA, vB);
        }
    }
}

// ================= kernel 2: recurrence (K = 50) =================
__global__ __launch_bounds__(NTH, 2)
void lstm_kernel(const float* __restrict__ x,   const float* __restrict__ Whh,
                 const float* __restrict__ W1,  const float* __restrict__ b1,
                 const float* __restrict__ W2,  const float* __restrict__ b2,
                 float* __restrict__ out)
{
    __shared__ __align__(16) float sZ[RR][KH];     // h (+pad), single buffer
    __shared__ __align__(16) float sG[RR][GG];     // pre-activation gates

    const int tid = threadIdx.x;
    const int b0  = blockIdx.x * RR;

    // zero h buffer (h0 = 0, pads stay 0)
    for (int i = tid; i < RR * KH; i += NTH) ((float*)sZ)[i] = 0.0f;

    // W_hh row j in registers (28 packed f32x2, zero-padded)
    const int j = (tid < GG) ? tid : 0;
    unsigned long long w[28];
    #pragma unroll
    for (int kk = 0; kk < 28; ++kk) {
        int k0 = 2 * kk, k1 = 2 * kk + 1;
        float lo = (tid < GG && k0 < HH) ? Whh[j * HH + k0] : 0.0f;
        float hi = (tid < GG && k1 < HH) ? Whh[j * HH + k1] : 0.0f;
        w[kk] = pk2(lo, hi);
    }

    // cell role (cr, cu); c0[:,0] = 1, register-resident
    const int cr = tid / HH;
    const int cu = tid - cr * HH;
    float creg = (tid < GG && cu == 0) ? 1.0f : 0.0f;

    // xg streaming pointers, one per row; prefetch t=0
    const float* __restrict__ p0 = g_xg + ((long)(b0 + 0) * TT) * GG + tid;
    const float* __restrict__ p1 = g_xg + ((long)(b0 + 1) * TT) * GG + tid;
    const float* __restrict__ p2 = g_xg + ((long)(b0 + 2) * TT) * GG + tid;
    const float* __restrict__ p3 = g_xg + ((long)(b0 + 3) * TT) * GG + tid;
    float c0v = 0.f, c1v = 0.f, c2v = 0.f, c3v = 0.f;
    if (tid < GG) { c0v = *p0; c1v = *p1; c2v = *p2; c3v = *p3; }
    __syncthreads();

    for (int t = 0; t < TT; ++t) {
        float n0 = 0.f, n1 = 0.f, n2 = 0.f, n3 = 0.f;
        if (tid < GG) {
            // prefetch xg[t+1] (consumed next step)
            if ((t + 1) < TT) {
                n0 = p0[(t + 1) * GG];
                n1 = p1[(t + 1) * GG];
                n2 = p2[(t + 1) * GG];
                n3 = p3[(t + 1) * GG];
            }
            // gemv: gate j for 4 rows over h (14 ull2 each)
            unsigned long long a0 = pk2(c0v, 0.f), a1 = pk2(c1v, 0.f);
            unsigned long long a2 = pk2(c2v, 0.f), a3 = pk2(c3v, 0.f);
            const ulonglong2* __restrict__ zb = (const ulonglong2*)&sZ[0][0];
            #pragma unroll
            for (int i = 0; i < 14; ++i) {
                ulonglong2 z0 = zb[ 0 + i];
                ulonglong2 z1 = zb[14 + i];
                ulonglong2 z2 = zb[28 + i];
                ulonglong2 z3 = zb[42 + i];
                unsigned long long wa = w[2 * i], wb = w[2 * i + 1];
                a0 = f2fma(wa, z0.x, a0); a0 = f2fma(wb, z0.y, a0);
                a1 = f2fma(wa, z1.x, a1); a1 = f2fma(wb, z1.y, a1);
                a2 = f2fma(wa, z2.x, a2); a2 = f2fma(wb, z2.y, a2);
                a3 = f2fma(wa, z3.x, a3); a3 = f2fma(wb, z3.y, a3);
            }
            float lo, hi;
            upk2(a0, lo, hi); sG[0][tid] = lo + hi;
            upk2(a1, lo, hi); sG[1][tid] = lo + hi;
            upk2(a2, lo, hi); sG[2][tid] = lo + hi;
            upk2(a3, lo, hi); sG[3][tid] = lo + hi;
        }
        __syncthreads();

        if (tid < GG) {
            float gi = sG[cr][         cu];
            float gf = sG[cr][    HH + cu];
            float gc = sG[cr][2 * HH + cu];
            float go = sG[cr][3 * HH + cu];
            float si = sig_f(gi);
            float sf = sig_f(gf);
            float tg = tanh_f(gc);
            float so = sig_f(go);
            creg = fmaf(sf, creg, si * tg);
            sZ[cr][cu] = so * tanh_f(creg);
        }
        __syncthreads();

        c0v = n0; c1v = n1; c2v = n2; c3v = n3;
    }

    // ================= MLP head =================
    if (tid < RR * 10) {
        int r = tid / 10, m = tid - (tid / 10) * 10;
        float s = b1[m];
        #pragma unroll
        for (int u = 0; u < HH; ++u)
            s = fmaf(sZ[r][u], W1[m * HH + u], s);
        sG[0][tid] = fmaxf(s, 0.0f);
    }
    __syncthreads();

    if (tid < RR) {
        float o = b2[0];
        #pragma unroll
        for (int m = 0; m < 10; ++m)
            o = fmaf(sG[0][tid * 10 + m], W2[m], o);
        out[b0 + tid] = o + x[((long)(b0 + tid) * TT + (TT - 1)) * FF + 0];
    }
}

extern "C" void kernel_launch(void* const* d_in, const int* in_sizes, int n_in,
                              void* d_out, int out_size)
{
    const float* x   = (const float*)d_in[0];
    const float* Wih = (const float*)d_in[1];
    const float* Whh = (const float*)d_in[2];
    const float* bih = (const float*)d_in[3];
    const float* bhh = (const float*)d_in[4];
    const float* W1  = (const float*)d_in[5];
    const float* b1  = (const float*)d_in[6];
    const float* W2  = (const float*)d_in[7];
    const float* b2  = (const float*)d_in[8];
    float* out = (float*)d_out;

    xg_kernel<<<NGRID1, NT1>>>(x, Wih, bih, bhh);
    lstm_kernel<<<NGRID, NTH>>>(x, Whh, W1, b1, W2, b2, out);
}

// round 12
// speedup vs baseline: 1.0278x; 1.0278x over previous
#include <cuda_runtime.h>

// LSTM B=1024 T=512 F=40 H=50 + MLP head. Round 12 (= R11 resubmit; R11 hit
// an infra failure, same as R9->R10 which ran unchanged on retry).
//
// Single fused kernel: x-projection folded into the recurrence's latency
// bubbles. 256 CTAs x 224 threads, RR=4 rows/CTA, 2 CTAs/SM (<=144 regs).
// Compute threads (tid<200 = gate j):
//   regs: W_hh row (28 f32x2) + W_ih row (20 f32x2) + bias.
//   Phase A of step t: gates(t) = xgc + W_hh . h(t-1)  (broadcast ld.shared
//   .v2.u64, 4 indep accum chains) INTERLEAVED with the independent
//   xgc(t+1) = bias + W_ih . x(t+1) from SMEM tile (4 more indep chains,
//   fills LDS-latency bubbles). Phase B: gate read from sG, MUFU
//   activations, register c-state, h -> sZ.
// Spare threads (tid 200..223): stage x(t+2) into a triple-buffered SMEM
//   tile (40 float4; write at t, read at t+1, rewrite at t+3 — always
//   barrier-separated). Two __syncthreads per step. No global scratch.

#define TT   512
#define FF   40
#define HH   50
#define GG   200
#define RR   4
#define KH   56           // padded h-K (50 + 6 pad) = 14 ull2
#define NTH  224
#define NGRID 256         // 1024 / RR

__device__ __forceinline__ unsigned long long pk2(float lo, float hi) {
    unsigned long long r;
    asm("mov.b64 %0, {%1, %2};" : "=l"(r) : "f"(lo), "f"(hi));
    return r;
}
__device__ __forceinline__ void upk2(unsigned long long v, float& lo, float& hi) {
    asm("mov.b64 {%0, %1}, %2;" : "=f"(lo), "=f"(hi) : "l"(v));
}
__device__ __forceinline__ unsigned long long f2fma(unsigned long long a,
                                                   unsigned long long b,
                                                   unsigned long long c) {
    unsigned long long d;
    asm("fma.rn.f32x2 %0, %1, %2, %3;" : "=l"(d) : "l"(a), "l"(b), "l"(c));
    return d;
}
__device__ __forceinline__ float tanh_f(float x) {
    float y;
    asm("tanh.approx.f32 %0, %1;" : "=f"(y) : "f"(x));
    return y;
}
__device__ __forceinline__ float sig_f(float x) {
    return fmaf(0.5f, tanh_f(0.5f * x), 0.5f);
}

__global__ __launch_bounds__(NTH, 2)
void lstm_kernel(const float* __restrict__ x,   const float* __restrict__ Wih,
                 const float* __restrict__ Whh, const float* __restrict__ bih,
                 const float* __restrict__ bhh, const float* __restrict__ W1,
                 const float* __restrict__ b1,  const float* __restrict__ W2,
                 const float* __restrict__ b2,  float* __restrict__ out)
{
    __shared__ __align__(16) float sZ[RR][KH];       // h (+pad)
    __shared__ __align__(16) float sG[RR][GG];       // pre-activation gates
    __shared__ __align__(16) float sX[3][RR][FF];    // x tile, triple-buffered
    __shared__ __align__(16) float sH[RR * 10];      // head scratch

    const int tid = threadIdx.x;
    const int b0  = blockIdx.x * RR;

    // zero h buffer (h0 = 0, pads stay 0)
    for (int i = tid; i < RR * KH; i += NTH) ((float*)sZ)[i] = 0.0f;

    const int j = (tid < GG) ? tid : 0;

    // W_hh row (28 packed f32x2, zero-padded to K=56)
    unsigned long long wh[28];
    #pragma unroll
    for (int kk = 0; kk < 28; ++kk) {
        int k0 = 2 * kk, k1 = 2 * kk + 1;
        float lo = (tid < GG && k0 < HH) ? Whh[j * HH + k0] : 0.0f;
        float hi = (tid < GG && k1 < HH) ? Whh[j * HH + k1] : 0.0f;
        wh[kk] = pk2(lo, hi);
    }
    // W_ih row (20 packed f32x2, exact K=40)
    unsigned long long wi[20];
    #pragma unroll
    for (int kk = 0; kk < 20; ++kk) {
        float lo = (tid < GG) ? Wih[j * FF + 2 * kk]     : 0.0f;
        float hi = (tid < GG) ? Wih[j * FF + 2 * kk + 1] : 0.0f;
        wi[kk] = pk2(lo, hi);
    }
    const float bj = (tid < GG) ? (bih[j] + bhh[j]) : 0.0f;

    // cell role (cr, cu); c0[:,0] = 1, register-resident
    const int cr = tid / HH;
    const int cu = tid - cr * HH;
    float creg = (tid < GG && cu == 0) ? 1.0f : 0.0f;

    // loader role: tid 200..223 cover 40 float4 slots (stride 24)
    const int li = tid - GG;
    const float4* __restrict__ xv = (const float4*)x;

    // prologue: stage x0 -> sX[0], x1 -> sX[1]
    if (tid >= GG) {
        #pragma unroll
        for (int s = li; s < RR * 10; s += 24) {
            int r = s / 10, q = s - 10 * r;
            ((float4*)&sX[0][r][0])[q] = xv[((long)(b0 + r) * TT + 0) * 10 + q];
            ((float4*)&sX[1][r][0])[q] = xv[((long)(b0 + r) * TT + 1) * 10 + q];
        }
    }
    __syncthreads();

    // xgc = bias + W_ih . x_0 for 4 rows
    float xgc[RR] = {0.f, 0.f, 0.f, 0.f};
    if (tid < GG) {
        #pragma unroll
        for (int r = 0; r < RR; ++r) {
            unsigned long long a = pk2(bj, 0.0f);
            const ulonglong2* __restrict__ xz = (const ulonglong2*)&sX[0][r][0];
            #pragma unroll
            for (int i = 0; i < 10; ++i) {
                ulonglong2 zv = xz[i];
                a = f2fma(wi[2 * i],     zv.x, a);
                a = f2fma(wi[2 * i + 1], zv.y, a);
            }
            float lo, hi; upk2(a, lo, hi); xgc[r] = lo + hi;
        }
    }

    // ================= recurrence =================
    for (int t = 0; t < TT; ++t) {
        if (tid < GG) {
            // -- h-gemv (critical path) + xg(t+1) (independent filler) --
            unsigned long long a0 = pk2(xgc[0], 0.f), a1 = pk2(xgc[1], 0.f);
            unsigned long long a2 = pk2(xgc[2], 0.f), a3 = pk2(xgc[3], 0.f);
            const ulonglong2* __restrict__ zb = (const ulonglong2*)&sZ[0][0];

            const int nbuf = (t + 1) % 3;
            unsigned long long g0 = pk2(bj, 0.f), g1 = g0, g2 = g0, g3 = g0;
            const ulonglong2* __restrict__ x0 = (const ulonglong2*)&sX[nbuf][0][0];
            const ulonglong2* __restrict__ x1 = (const ulonglong2*)&sX[nbuf][1][0];
            const ulonglong2* __restrict__ x2 = (const ulonglong2*)&sX[nbuf][2][0];
            const ulonglong2* __restrict__ x3 = (const ulonglong2*)&sX[nbuf][3][0];

            #pragma unroll
            for (int i = 0; i < 14; ++i) {
                ulonglong2 z0 = zb[ 0 + i];
                ulonglong2 z1 = zb[14 + i];
                ulonglong2 z2 = zb[28 + i];
                ulonglong2 z3 = zb[42 + i];
                unsigned long long wa = wh[2 * i], wb = wh[2 * i + 1];
                a0 = f2fma(wa, z0.x, a0); a0 = f2fma(wb, z0.y, a0);
                a1 = f2fma(wa, z1.x, a1); a1 = f2fma(wb, z1.y, a1);
                a2 = f2fma(wa, z2.x, a2); a2 = f2fma(wb, z2.y, a2);
                a3 = f2fma(wa, z3.x, a3); a3 = f2fma(wb, z3.y, a3);
                if (i < 10) {       // interleaved independent xg chains
                    ulonglong2 y0 = x0[i], y1 = x1[i], y2 = x2[i], y3 = x3[i];
                    unsigned long long va = wi[2 * i], vb = wi[2 * i + 1];
                    g0 = f2fma(va, y0.x, g0); g0 = f2fma(vb, y0.y, g0);
                    g1 = f2fma(va, y1.x, g1); g1 = f2fma(vb, y1.y, g1);
                    g2 = f2fma(va, y2.x, g2); g2 = f2fma(vb, y2.y, g2);
                    g3 = f2fma(va, y3.x, g3); g3 = f2fma(vb, y3.y, g3);
                }
            }
            float lo, hi;
            upk2(a0, lo, hi); sG[0][tid] = lo + hi;
            upk2(a1, lo, hi); sG[1][tid] = lo + hi;
            upk2(a2, lo, hi); sG[2][tid] = lo + hi;
            upk2(a3, lo, hi); sG[3][tid] = lo + hi;
            upk2(g0, lo, hi); xgc[0] = lo + hi;
            upk2(g1, lo, hi); xgc[1] = lo + hi;
            upk2(g2, lo, hi); xgc[2] = lo + hi;
            upk2(g3, lo, hi); xgc[3] = lo + hi;
        } else if ((t + 2) < TT) {
            // stage x(t+2) -> sX[(t+2)%3] (read next step; barrier-separated)
            const int wbuf = (t + 2) % 3;
            #pragma unroll
            for (int s = li; s < RR * 10; s += 24) {
                int r = s / 10, q = s - 10 * r;
                ((float4*)&sX[wbuf][r][0])[q] =
                    xv[((long)(b0 + r) * TT + (t + 2)) * 10 + q];
            }
        }
        __syncthreads();

        // -- phase B: cell update --
        if (tid < GG) {
            float gi = sG[cr][         cu];
            float gf = sG[cr][    HH + cu];
            float gc = sG[cr][2 * HH + cu];
            float go = sG[cr][3 * HH + cu];
            float si = sig_f(gi);
            float sf = sig_f(gf);
            float tg = tanh_f(gc);
            float so = sig_f(go);
            creg = fmaf(sf, creg, si * tg);
            sZ[cr][cu] = so * tanh_f(creg);
        }
        __syncthreads();
    }

    // ================= MLP head =================
    if (tid < RR * 10) {
        int r = tid / 10, m = tid - (tid / 10) * 10;
        float s = b1[m];
        #pragma unroll
        for (int u = 0; u < HH; ++u)
            s = fmaf(sZ[r][u], W1[m * HH + u], s);
        sH[tid] = fmaxf(s, 0.0f);
    }
    __syncthreads();

    if (tid < RR) {
        float o = b2[0];
        #pragma unroll
        for (int m = 0; m < 10; ++m)
            o = fmaf(sH[tid * 10 + m], W2[m], o);
        out[b0 + tid] = o + x[((long)(b0 + tid) * TT + (TT - 1)) * FF + 0];
    }
}

extern "C" void kernel_launch(void* const* d_in, const int* in_sizes, int n_in,
                              void* d_out, int out_size)
{
    const float* x   = (const float*)d_in[0];
    const float* Wih = (const float*)d_in[1];
    const float* Whh = (const float*)d_in[2];
    const float* bih = (const float*)d_in[3];
    const float* bhh = (const float*)d_in[4];
    const float* W1  = (const float*)d_in[5];
    const float* b1  = (const float*)d_in[6];
    const float* W2  = (const float*)d_in[7];
    const float* b2  = (const float*)d_in[8];
    float* out = (float*)d_out;

    lstm_kernel<<<NGRID, NTH>>>(x, Wih, Whh, bih, bhh, W1, b1, W2, b2, out);
}